// round 14
// baseline (speedup 1.0000x reference)
#include <cuda_runtime.h>
#include <math.h>
#include <limits.h>

#define NMAX 200000
#define DM   128
#define VOXQ 8
#define NC   96        // off-logit columns

// ---------------- device globals (scratch; no allocations allowed) ----------
__device__ int g_min3[3];
__device__ int g_max3[3];
__device__ int g_count;
__device__ float g_wnml_raw;   // max column 2-norm * 1.02 * 1.1 / 1024

struct MSParams {
    int   minc[3];
    float rcf[3];
    float rv0f, rv1f;
    float wnml;
};
__device__ MSParams g_p;

__device__ int g_active[(size_t)NMAX];        // candidate row list

// ---------------- helpers ----------------------------------------------------
__device__ __forceinline__ float cvt_tf32(float x) {
    unsigned o;
    asm("cvt.rna.tf32.f32 %0, %1;" : "=r"(o) : "f"(x));
    return __uint_as_float(o);
}

__device__ __forceinline__ void mma_tf32(float* c,
    unsigned a0, unsigned a1, unsigned a2, unsigned a3,
    unsigned b0, unsigned b1)
{
    asm volatile(
        "mma.sync.aligned.m16n8k8.row.col.f32.tf32.tf32.f32 "
        "{%0,%1,%2,%3}, {%4,%5,%6,%7}, {%8,%9}, {%0,%1,%2,%3};"
        : "+f"(c[0]), "+f"(c[1]), "+f"(c[2]), "+f"(c[3])
        : "r"(a0), "r"(a1), "r"(a2), "r"(a3), "r"(b0), "r"(b1));
}

// ---------------- setup: init globals + W_off column-norm max (1 block) ------
__global__ void k_setup(const float* __restrict__ W_off) {
    __shared__ float cn[NC];
    int tid = threadIdx.x;

    if (tid < 3) {
        g_min3[tid] = INT_MAX;
        g_max3[tid] = INT_MIN;
    }
    if (tid == 0) g_count = 0;

    if (tid < NC) {
        float s = 0.f;
        #pragma unroll 8
        for (int k = 0; k < DM; k++) {
            float v = W_off[k * NC + tid];
            s += v * v;
        }
        cn[tid] = sqrtf(s);
    }
    __syncthreads();
    if (tid == 0) {
        float m = 0.f;
        for (int i = 0; i < NC; i++) m = fmaxf(m, cn[i]);
        g_wnml_raw = m * 1.02f * (1.1f / 1024.0f);
    }
}

// ---------------- minmax over coords -----------------------------------------
__global__ void k_minmax(const int* __restrict__ coords, int n) {
    int lmin0 = INT_MAX, lmin1 = INT_MAX, lmin2 = INT_MAX;
    int lmax0 = INT_MIN, lmax1 = INT_MIN, lmax2 = INT_MIN;
    for (int i = blockIdx.x * blockDim.x + threadIdx.x; i < n; i += gridDim.x * blockDim.x) {
        int c0 = coords[3*i + 0], c1 = coords[3*i + 1], c2 = coords[3*i + 2];
        lmin0 = min(lmin0, c0); lmax0 = max(lmax0, c0);
        lmin1 = min(lmin1, c1); lmax1 = max(lmax1, c1);
        lmin2 = min(lmin2, c2); lmax2 = max(lmax2, c2);
    }
    #pragma unroll
    for (int o = 16; o > 0; o >>= 1) {
        lmin0 = min(lmin0, __shfl_xor_sync(0xffffffffu, lmin0, o));
        lmin1 = min(lmin1, __shfl_xor_sync(0xffffffffu, lmin1, o));
        lmin2 = min(lmin2, __shfl_xor_sync(0xffffffffu, lmin2, o));
        lmax0 = max(lmax0, __shfl_xor_sync(0xffffffffu, lmax0, o));
        lmax1 = max(lmax1, __shfl_xor_sync(0xffffffffu, lmax1, o));
        lmax2 = max(lmax2, __shfl_xor_sync(0xffffffffu, lmax2, o));
    }
    if ((threadIdx.x & 31) == 0) {
        atomicMin(&g_min3[0], lmin0); atomicMin(&g_min3[1], lmin1); atomicMin(&g_min3[2], lmin2);
        atomicMax(&g_max3[0], lmax0); atomicMax(&g_max3[1], lmax1); atomicMax(&g_max3[2], lmax2);
    }
}

// ---------------- params (1 thread) ------------------------------------------
__global__ void k_params(int n) {
    if (threadIdx.x == 0 && blockIdx.x == 0) {
        int r0 = g_max3[0] - g_min3[0];
        int r1 = g_max3[1] - g_min3[1];
        int r2 = g_max3[2] - g_min3[2];
        g_p.minc[0] = g_min3[0]; g_p.minc[1] = g_min3[1]; g_p.minc[2] = g_min3[2];
        g_p.rcf[0] = (float)r0; g_p.rcf[1] = (float)r1; g_p.rcf[2] = (float)r2;
        g_p.rv0f = (float)(r0 / VOXQ + 1);
        g_p.rv1f = (float)(r1 / VOXQ + 1);
        g_p.wnml = g_wnml_raw;
    }
}

// ---------------- fused TF32 screen: 128 rows x 96 cols per CTA --------------
// 256 threads = 8 warps; warp w owns rows w*16..w*16+15, all 12 n-tiles.
// Double-buffered As/Ws -> ONE sync per k-chunk. Certified margin -> candidates.
__global__ __launch_bounds__(256, 2)
void k_screen(const float* __restrict__ A, const float* __restrict__ W1,
              const float* __restrict__ b1, const float* __restrict__ b_out,
              int* __restrict__ act_list, float* __restrict__ out, int n)
{
    __shared__ __align__(16) float As[2][16 * 136];   // tf32 bits, As[buf][k][row]
    __shared__ __align__(16) float Ws[2][16 * 104];   // tf32 bits, Ws[buf][k][col]
    __shared__ float qn[128];
    __shared__ float sboff[NC];
    __shared__ __align__(16) float sbout[128];
    __shared__ unsigned rowmask[128 * 3];

    int m0 = blockIdx.x * 128;
    int tid = threadIdx.x;
    int warp = tid >> 5, lane = tid & 31;
    int lk = lane & 3, lr = lane >> 2;

    if (tid < 128) sbout[tid] = b_out[tid];
    if (tid < NC)  sboff[tid] = b1[tid];
    rowmask[tid] = 0u; if (tid < 128) rowmask[256 + tid] = 0u;

    float acc[12][4];
    #pragma unroll
    for (int j = 0; j < 12; j++)
        #pragma unroll
        for (int i = 0; i < 4; i++) acc[j][i] = 0.f;

    // staging roles
    int arow = tid >> 1;                 // 0..127
    int ahalf = (tid & 1) * 8;           // k offset within chunk
    int gr = m0 + arow;
    const float* aRow = (gr < n) ? (A + (size_t)gr * DM + ahalf) : (const float*)0;
    int s1 = tid, s2 = tid + 256;        // W float4 slots (384 total)
    int wr1 = s1 / 24, wc1 = (s1 % 24) * 4;
    int wr2 = s2 / 24, wc2 = (s2 % 24) * 4;
    bool hasW2 = (tid < 128);

    float sq = 0.f;

    // ---- prologue: load + stage chunk 0 into buf 0 ----
    {
        float4 pa0 = make_float4(0,0,0,0), pa1 = pa0;
        if (aRow) { pa0 = *(const float4*)(aRow); pa1 = *(const float4*)(aRow + 4); }
        float4 pw1f = *(const float4*)(W1 + (size_t)wr1 * NC + wc1);
        float av[8] = {pa0.x, pa0.y, pa0.z, pa0.w, pa1.x, pa1.y, pa1.z, pa1.w};
        #pragma unroll
        for (int j = 0; j < 8; j++) {
            sq += av[j] * av[j];
            As[0][(ahalf + j) * 136 + arow] = cvt_tf32(av[j]);
        }
        Ws[0][wr1 * 104 + wc1 + 0] = cvt_tf32(pw1f.x);
        Ws[0][wr1 * 104 + wc1 + 1] = cvt_tf32(pw1f.y);
        Ws[0][wr1 * 104 + wc1 + 2] = cvt_tf32(pw1f.z);
        Ws[0][wr1 * 104 + wc1 + 3] = cvt_tf32(pw1f.w);
        if (hasW2) {
            float4 pw2f = *(const float4*)(W1 + (size_t)wr2 * NC + wc2);
            Ws[0][wr2 * 104 + wc2 + 0] = cvt_tf32(pw2f.x);
            Ws[0][wr2 * 104 + wc2 + 1] = cvt_tf32(pw2f.y);
            Ws[0][wr2 * 104 + wc2 + 2] = cvt_tf32(pw2f.z);
            Ws[0][wr2 * 104 + wc2 + 3] = cvt_tf32(pw2f.w);
        }
    }
    __syncthreads();

    int rowbase = warp * 16;

    #pragma unroll 1
    for (int kb = 0; kb < 8; kb++) {
        int cur = kb & 1, nxt = cur ^ 1;

        // stage chunk kb+1 into the other buffer; its previous readers were
        // ordered by the barrier at the end of iteration kb-1
        if (kb < 7) {
            int ko = (kb + 1) * 16;
            float4 pa0 = make_float4(0,0,0,0), pa1 = pa0;
            if (aRow) { pa0 = *(const float4*)(aRow + ko); pa1 = *(const float4*)(aRow + ko + 4); }
            float4 pw1f = *(const float4*)(W1 + (size_t)(ko + wr1) * NC + wc1);
            float av[8] = {pa0.x, pa0.y, pa0.z, pa0.w, pa1.x, pa1.y, pa1.z, pa1.w};
            #pragma unroll
            for (int j = 0; j < 8; j++) {
                sq += av[j] * av[j];
                As[nxt][(ahalf + j) * 136 + arow] = cvt_tf32(av[j]);
            }
            Ws[nxt][wr1 * 104 + wc1 + 0] = cvt_tf32(pw1f.x);
            Ws[nxt][wr1 * 104 + wc1 + 1] = cvt_tf32(pw1f.y);
            Ws[nxt][wr1 * 104 + wc1 + 2] = cvt_tf32(pw1f.z);
            Ws[nxt][wr1 * 104 + wc1 + 3] = cvt_tf32(pw1f.w);
            if (hasW2) {
                float4 pw2f = *(const float4*)(W1 + (size_t)(ko + wr2) * NC + wc2);
                Ws[nxt][wr2 * 104 + wc2 + 0] = cvt_tf32(pw2f.x);
                Ws[nxt][wr2 * 104 + wc2 + 1] = cvt_tf32(pw2f.y);
                Ws[nxt][wr2 * 104 + wc2 + 2] = cvt_tf32(pw2f.z);
                Ws[nxt][wr2 * 104 + wc2 + 3] = cvt_tf32(pw2f.w);
            }
        }

        // mma mainloop: 2 k8-steps x 12 n-tiles from buffer `cur`
        #pragma unroll
        for (int ks = 0; ks < 2; ks++) {
            int k8 = ks * 8;
            unsigned a0 = __float_as_uint(As[cur][(k8 + lk    ) * 136 + rowbase + lr]);
            unsigned a1 = __float_as_uint(As[cur][(k8 + lk    ) * 136 + rowbase + lr + 8]);
            unsigned a2 = __float_as_uint(As[cur][(k8 + lk + 4) * 136 + rowbase + lr]);
            unsigned a3 = __float_as_uint(As[cur][(k8 + lk + 4) * 136 + rowbase + lr + 8]);
            #pragma unroll
            for (int j = 0; j < 12; j++) {
                unsigned b0 = __float_as_uint(Ws[cur][(k8 + lk    ) * 104 + j*8 + lr]);
                unsigned b1v = __float_as_uint(Ws[cur][(k8 + lk + 4) * 104 + j*8 + lr]);
                mma_tf32(acc[j], a0, a1, a2, a3, b0, b1v);
            }
        }
        __syncthreads();   // single barrier: next-buf staged AND cur reads done
    }

    // exact per-row ||q||: thread t and t^1 hold the two halves of row t>>1
    sq += __shfl_xor_sync(0xffffffffu, sq, 1);
    if ((tid & 1) == 0) qn[arow] = sqrtf(sq) * 1.02f;
    __syncthreads();

    // ---- epilogue: conservative window test per (row, col) ----
    float rc[3] = { g_p.rcf[0], g_p.rcf[1], g_p.rcf[2] };
    float wnml = g_p.wnml;
    int r0l = warp * 16 + lr, r1l = r0l + 8;
    float ml0 = qn[r0l] * wnml;
    float ml1 = qn[r1l] * wnml;
    unsigned msk0[3] = {0u,0u,0u}, msk1[3] = {0u,0u,0u};

    #pragma unroll
    for (int j = 0; j < 12; j++) {
        int cA = j*8 + 2*lk, cB = cA + 1;
        int dA = cA % 3, dB = cB % 3;
        float sdA = 0.5f * rc[dA], sdB = 0.5f * rc[dB];
        float bA = sboff[cA], bB = sboff[cB];

        float tA0 = (acc[j][0] + bA) * sdA;
        float tB0 = (acc[j][1] + bB) * sdB;
        float tA1 = (acc[j][2] + bA) * sdA;
        float tB1 = (acc[j][3] + bB) * sdB;
        float mA0 = ml0 * sdA + 1e-3f, mB0 = ml0 * sdB + 1e-3f;
        float mA1 = ml1 * sdA + 1e-3f, mB1 = ml1 * sdB + 1e-3f;

        if (tA0 > -1.f - mA0 && tA0 < 8.f + mA0) msk0[cA >> 5] |= 1u << (cA & 31);
        if (tB0 > -1.f - mB0 && tB0 < 8.f + mB0) msk0[cB >> 5] |= 1u << (cB & 31);
        if (tA1 > -1.f - mA1 && tA1 < 8.f + mA1) msk1[cA >> 5] |= 1u << (cA & 31);
        if (tB1 > -1.f - mB1 && tB1 < 8.f + mB1) msk1[cB >> 5] |= 1u << (cB & 31);
    }
    #pragma unroll
    for (int w = 0; w < 3; w++) {
        if (msk0[w]) atomicOr(&rowmask[r0l * 3 + w], msk0[w]);
        if (msk1[w]) atomicOr(&rowmask[r1l * 3 + w], msk1[w]);
    }
    __syncthreads();

    // candidate rows: exists p with bits 3p, 3p+1, 3p+2 all set
    if (tid < 128) {
        int row = m0 + tid;
        if (row < n) {
            unsigned w0 = rowmask[tid*3], w1 = rowmask[tid*3+1], w2 = rowmask[tid*3+2];
            if (w0 | w1 | w2) {
                bool any = false;
                #pragma unroll
                for (int p = 0; p < 32; p++) {
                    int c = 3 * p;
                    unsigned q0b = ((c < 32 ? w0 : (c < 64 ? w1 : w2)) >> (c & 31)) & 1u;
                    int c1i = c + 1;
                    unsigned q1b = ((c1i < 32 ? w0 : (c1i < 64 ? w1 : w2)) >> (c1i & 31)) & 1u;
                    int c2i = c + 2;
                    unsigned q2b = ((c2i < 32 ? w0 : (c2i < 64 ? w1 : w2)) >> (c2i & 31)) & 1u;
                    any |= (q0b & q1b & q2b) != 0u;
                }
                if (any) {
                    int slot = atomicAdd(&g_count, 1);
                    act_list[slot] = row;
                }
            }
        }
    }

    // fill out = b_out with streaming stores (exact for non-candidates;
    // candidates overwritten by k_active in the same stream)
    for (int idx = tid; idx < 128 * 32; idx += 256) {
        int r  = idx >> 5;
        int c4 = (idx & 31) << 2;
        int orow = m0 + r;
        if (orow < n)
            __stcs((float4*)(out + (size_t)orow * DM + c4), *(const float4*)&sbout[c4]);
    }
}

// ---------------- active rows: full exact fp32 recompute per row -------------
__global__ __launch_bounds__(128)
void k_active(const float* __restrict__ query, const int* __restrict__ coords,
              const float* __restrict__ value_fea,
              const float* __restrict__ W_off,  const float* __restrict__ b_off,
              const float* __restrict__ W_attn, const float* __restrict__ b_attn,
              const float* __restrict__ W_val,  const float* __restrict__ b_val,
              const float* __restrict__ W_out,  const float* __restrict__ b_out,
              const int* __restrict__ act_list, float* __restrict__ out, int n)
{
    __shared__ float sq[DM];
    __shared__ float slog[DM];
    __shared__ float sv[DM];
    __shared__ float spre[DM];
    __shared__ float sw[8];
    __shared__ int   sgi1;

    int tid = threadIdx.x;
    int cnt = g_count;

    for (int idx = blockIdx.x; idx < cnt; idx += gridDim.x) {
        int row = act_list[idx];
        sq[tid] = query[(size_t)row * DM + tid];
        __syncthreads();

        // exact logits [off | attn]
        {
            float a = 0.f;
            if (tid < 96) {
                #pragma unroll 8
                for (int k = 0; k < DM; k++)
                    a = fmaf(sq[k], W_off[k * 96 + tid], a);
                a += b_off[tid];
            } else {
                int c = tid - 96;
                #pragma unroll 8
                for (int k = 0; k < DM; k++)
                    a = fmaf(sq[k], W_attn[k * 32 + c], a);
                a += b_attn[c];
            }
            slog[tid] = a;
        }
        __syncthreads();

        // mask + softmax per head; gather index
        if (tid < 8) {
            int h = tid;
            float l[4], e[4];
            #pragma unroll
            for (int p = 0; p < 4; p++) l[p] = slog[96 + h*4 + p];
            float mx = fmaxf(fmaxf(l[0], l[1]), fmaxf(l[2], l[3]));
            float s = 0.f;
            #pragma unroll
            for (int p = 0; p < 4; p++) { e[p] = expf(l[p] - mx); s += e[p]; }
            float num = 0.f;
            #pragma unroll
            for (int p = 0; p < 4; p++) {
                int base = (h*4 + p) * 3;
                float t0 = (slog[base + 0] * g_p.rcf[0]) * 0.5f;
                float t1 = (slog[base + 1] * g_p.rcf[1]) * 0.5f;
                float t2 = (slog[base + 2] * g_p.rcf[2]) * 0.5f;
                int a0 = (int)t0, a1 = (int)t1, a2 = (int)t2;  // trunc toward 0
                unsigned u = (unsigned)a0 | (unsigned)a1 | (unsigned)a2;
                if (u < 8u) num += e[p];
            }
            sw[h] = num / s;
        }
        if (tid == 0) {
            int c0 = coords[3*row + 0], c1 = coords[3*row + 1], c2 = coords[3*row + 2];
            float i0 = (float)(c0 - g_p.minc[0]) * 0.125f;
            float i1 = (float)(c1 - g_p.minc[1]) * 0.125f;
            float i2 = (float)(c2 - g_p.minc[2]) * 0.125f;
            float flat = i0 * g_p.rv1f * g_p.rv0f + i1 * g_p.rv0f + i2;
            int gi = (int)floorf(flat);
            gi = gi < 0 ? 0 : (gi > n - 1 ? n - 1 : gi);
            sgi1 = gi;
        }
        __syncthreads();

        sv[tid] = value_fea[(size_t)sgi1 * DM + tid];
        __syncthreads();

        // value GEMV + head-weight scale
        {
            float a = 0.f;
            #pragma unroll 8
            for (int k = 0; k < DM; k++)
                a = fmaf(sv[k], W_val[k * DM + tid], a);
            spre[tid] = (a + b_val[tid]) * sw[tid >> 4];
        }
        __syncthreads();

        // out GEMV
        {
            float a = 0.f;
            #pragma unroll 8
            for (int k = 0; k < DM; k++)
                a = fmaf(spre[k], W_out[k * DM + tid], a);
            out[(size_t)row * DM + tid] = a + b_out[tid];
        }
        __syncthreads();
    }
}

// ---------------- launcher ---------------------------------------------------
extern "C" void kernel_launch(void* const* d_in, const int* in_sizes, int n_in,
                              void* d_out, int out_size)
{
    const float* query     = (const float*)d_in[0];
    const float* value_fea = (const float*)d_in[1];
    const int*   coords    = (const int*)  d_in[2];
    const float* W_off     = (const float*)d_in[3];
    const float* b_off     = (const float*)d_in[4];
    const float* W_attn    = (const float*)d_in[5];
    const float* b_attn    = (const float*)d_in[6];
    const float* W_val     = (const float*)d_in[7];
    const float* b_val     = (const float*)d_in[8];
    const float* W_out     = (const float*)d_in[9];
    const float* b_out     = (const float*)d_in[10];
    float* out = (float*)d_out;

    int n = in_sizes[0] / DM;
    if (n > NMAX) n = NMAX;

    int* gact = nullptr;
    cudaGetSymbolAddress((void**)&gact, g_active);

    int nb = (n + 127) / 128;

    // 5 launches total
    k_setup <<<1, 256>>>(W_off);                 // init + W column-norm max
    k_minmax<<<592, 256>>>(coords, n);
    k_params<<<1, 1>>>(n);

    // TF32 tensor-core screen (certified margin) + out=b_out fill
    k_screen<<<nb, 256>>>(query, W_off, b_off, b_out, gact, out, n);

    // exact end-to-end recompute of candidate rows
    k_active<<<512, 128>>>(query, coords, value_fea,
                           W_off, b_off, W_attn, b_attn,
                           W_val, b_val, W_out, b_out,
                           gact, out, n);
}

// round 15
// speedup vs baseline: 1.0065x; 1.0065x over previous
#include <cuda_runtime.h>
#include <math.h>
#include <limits.h>

#define NMAX 200000
#define DM   128
#define VOXQ 8
#define NC   96        // off-logit columns
#define SA   20        // A smem row stride (floats): conflict-free + 16B aligned
#define SW   104       // W smem row stride (floats)

// ---------------- device globals (scratch; no allocations allowed) ----------
__device__ int g_min3[3];
__device__ int g_max3[3];
__device__ int g_count;
__device__ float g_wnml_raw;   // max column 2-norm * 1.02 * 2.2/1024 (truncation margin)

struct MSParams {
    int   minc[3];
    float rcf[3];
    float rv0f, rv1f;
    float wnml;
};
__device__ MSParams g_p;

__device__ int g_active[(size_t)NMAX];        // candidate row list

// ---------------- helpers ----------------------------------------------------
__device__ __forceinline__ void mma_tf32(float* c,
    unsigned a0, unsigned a1, unsigned a2, unsigned a3,
    unsigned b0, unsigned b1)
{
    asm volatile(
        "mma.sync.aligned.m16n8k8.row.col.f32.tf32.tf32.f32 "
        "{%0,%1,%2,%3}, {%4,%5,%6,%7}, {%8,%9}, {%0,%1,%2,%3};"
        : "+f"(c[0]), "+f"(c[1]), "+f"(c[2]), "+f"(c[3])
        : "r"(a0), "r"(a1), "r"(a2), "r"(a3), "r"(b0), "r"(b1));
}

#define CP_ASYNC16(dst_u32, src_ptr) \
    asm volatile("cp.async.ca.shared.global [%0], [%1], 16;" \
                 :: "r"(dst_u32), "l"(src_ptr))
#define CP_COMMIT() asm volatile("cp.async.commit_group;")
#define CP_WAIT(N)  asm volatile("cp.async.wait_group %0;" :: "n"(N))

// ---------------- setup: init globals + W_off column-norm max (1 block) ------
__global__ void k_setup(const float* __restrict__ W_off) {
    __shared__ float cn[NC];
    int tid = threadIdx.x;

    if (tid < 3) {
        g_min3[tid] = INT_MAX;
        g_max3[tid] = INT_MIN;
    }
    if (tid == 0) g_count = 0;

    if (tid < NC) {
        float s = 0.f;
        #pragma unroll 8
        for (int k = 0; k < DM; k++) {
            float v = W_off[k * NC + tid];
            s += v * v;
        }
        cn[tid] = sqrtf(s);
    }
    __syncthreads();
    if (tid == 0) {
        float m = 0.f;
        for (int i = 0; i < NC; i++) m = fmaxf(m, cn[i]);
        // truncation-mode tf32 (no cvt): per-operand rel err <= 2^-10 -> 2.2/1024 covers
        g_wnml_raw = m * 1.02f * (2.2f / 1024.0f);
    }
}

// ---------------- minmax over coords -----------------------------------------
__global__ void k_minmax(const int* __restrict__ coords, int n) {
    int lmin0 = INT_MAX, lmin1 = INT_MAX, lmin2 = INT_MAX;
    int lmax0 = INT_MIN, lmax1 = INT_MIN, lmax2 = INT_MIN;
    for (int i = blockIdx.x * blockDim.x + threadIdx.x; i < n; i += gridDim.x * blockDim.x) {
        int c0 = coords[3*i + 0], c1 = coords[3*i + 1], c2 = coords[3*i + 2];
        lmin0 = min(lmin0, c0); lmax0 = max(lmax0, c0);
        lmin1 = min(lmin1, c1); lmax1 = max(lmax1, c1);
        lmin2 = min(lmin2, c2); lmax2 = max(lmax2, c2);
    }
    #pragma unroll
    for (int o = 16; o > 0; o >>= 1) {
        lmin0 = min(lmin0, __shfl_xor_sync(0xffffffffu, lmin0, o));
        lmin1 = min(lmin1, __shfl_xor_sync(0xffffffffu, lmin1, o));
        lmin2 = min(lmin2, __shfl_xor_sync(0xffffffffu, lmin2, o));
        lmax0 = max(lmax0, __shfl_xor_sync(0xffffffffu, lmax0, o));
        lmax1 = max(lmax1, __shfl_xor_sync(0xffffffffu, lmax1, o));
        lmax2 = max(lmax2, __shfl_xor_sync(0xffffffffu, lmax2, o));
    }
    if ((threadIdx.x & 31) == 0) {
        atomicMin(&g_min3[0], lmin0); atomicMin(&g_min3[1], lmin1); atomicMin(&g_min3[2], lmin2);
        atomicMax(&g_max3[0], lmax0); atomicMax(&g_max3[1], lmax1); atomicMax(&g_max3[2], lmax2);
    }
}

// ---------------- params (1 thread) ------------------------------------------
__global__ void k_params(int n) {
    if (threadIdx.x == 0 && blockIdx.x == 0) {
        int r0 = g_max3[0] - g_min3[0];
        int r1 = g_max3[1] - g_min3[1];
        int r2 = g_max3[2] - g_min3[2];
        g_p.minc[0] = g_min3[0]; g_p.minc[1] = g_min3[1]; g_p.minc[2] = g_min3[2];
        g_p.rcf[0] = (float)r0; g_p.rcf[1] = (float)r1; g_p.rcf[2] = (float)r2;
        g_p.rv0f = (float)(r0 / VOXQ + 1);
        g_p.rv1f = (float)(r1 / VOXQ + 1);
        g_p.wnml = g_wnml_raw;
    }
}

// ---------------- fused TF32 screen: 128 rows x 96 cols per CTA --------------
// 256 threads, 3 CTAs/SM. A: row-major smem (stride 20), staged via regs
// (computes exact ||q||), raw fp32 bits (no cvt). W: cp.async double-buffered.
__global__ __launch_bounds__(256, 3)
void k_screen(const float* __restrict__ A, const float* __restrict__ W1,
              const float* __restrict__ b1, const float* __restrict__ b_out,
              int* __restrict__ act_list, float* __restrict__ out, int n)
{
    __shared__ __align__(16) float As[128 * SA];      // A chunk, row-major
    __shared__ __align__(16) float Ws[2][16 * SW];    // W chunk, k-major, dbl-buf
    __shared__ float qn[128];
    __shared__ float sboff[NC];
    __shared__ __align__(16) float sbout[128];
    __shared__ unsigned rowmask[128 * 3];

    int m0 = blockIdx.x * 128;
    int tid = threadIdx.x;
    int warp = tid >> 5, lane = tid & 31;
    int lk = lane & 3, lr = lane >> 2;

    if (tid < 128) sbout[tid] = b_out[tid];
    if (tid < NC)  sboff[tid] = b1[tid];
    rowmask[tid] = 0u; if (tid < 128) rowmask[256 + tid] = 0u;

    float acc[12][4];
    #pragma unroll
    for (int j = 0; j < 12; j++)
        #pragma unroll
        for (int i = 0; i < 4; i++) acc[j][i] = 0.f;

    // staging roles
    int arow = tid >> 1;                 // 0..127
    int ahalf = (tid & 1) * 8;           // k offset within chunk
    int gr = m0 + arow;
    const float* aRow = (gr < n) ? (A + (size_t)gr * DM + ahalf) : (const float*)0;
    // W cp.async slots: 384 float4 slots (16 k x 96 c / 4)
    int s1 = tid, s2 = tid + 256;
    int wr1 = s1 / 24, wc1 = (s1 % 24) * 4;
    int wr2 = s2 / 24, wc2 = (s2 % 24) * 4;
    bool hasW2 = (tid < 128);

    unsigned wsm[2];
    wsm[0] = (unsigned)__cvta_generic_to_shared(&Ws[0][0]);
    wsm[1] = (unsigned)__cvta_generic_to_shared(&Ws[1][0]);
    unsigned wdst1_0 = wsm[0] + (wr1 * SW + wc1) * 4;
    unsigned wdst1_1 = wsm[1] + (wr1 * SW + wc1) * 4;
    unsigned wdst2_0 = wsm[0] + (wr2 * SW + wc2) * 4;
    unsigned wdst2_1 = wsm[1] + (wr2 * SW + wc2) * 4;

    float sq = 0.f;

    // prologue: A chunk0 regs + W chunk0 cp.async (group 0)
    float4 pa0 = make_float4(0,0,0,0), pa1 = pa0;
    if (aRow) { pa0 = *(const float4*)(aRow); pa1 = *(const float4*)(aRow + 4); }
    CP_ASYNC16(wdst1_0, W1 + (size_t)wr1 * NC + wc1);
    if (hasW2) CP_ASYNC16(wdst2_0, W1 + (size_t)wr2 * NC + wc2);
    CP_COMMIT();

    int rowbase = warp * 16;
    float* aBase = &As[arow * SA + ahalf];

    #pragma unroll 1
    for (int kb = 0; kb < 8; kb++) {
        int cur = kb & 1;

        // stage A chunk kb (raw fp32; exact ||q|| accumulation)
        sq += pa0.x*pa0.x + pa0.y*pa0.y + pa0.z*pa0.z + pa0.w*pa0.w
            + pa1.x*pa1.x + pa1.y*pa1.y + pa1.z*pa1.z + pa1.w*pa1.w;
        *(float4*)(aBase)     = pa0;
        *(float4*)(aBase + 4) = pa1;

        // issue W chunk kb+1 into the other buffer (safe: its readers finished
        // before the final sync of iteration kb-1)
        if (kb < 7) {
            int ko = (kb + 1) * 16;
            CP_ASYNC16((cur ? wdst1_0 : wdst1_1), W1 + (size_t)(ko + wr1) * NC + wc1);
            if (hasW2) CP_ASYNC16((cur ? wdst2_0 : wdst2_1), W1 + (size_t)(ko + wr2) * NC + wc2);
            CP_COMMIT();
            CP_WAIT(1);          // W chunk kb complete (kb+1 may be in flight)
        } else {
            CP_WAIT(0);          // last chunk: everything complete
        }
        __syncthreads();

        // prefetch A chunk kb+1
        if (kb < 7) {
            int ko = (kb + 1) * 16;
            if (aRow) { pa0 = *(const float4*)(aRow + ko); pa1 = *(const float4*)(aRow + ko + 4); }
        }

        // mma: 2 k8-steps x 12 n-tiles; A row-major scalar reads (conflict-free)
        const float* wb = &Ws[cur][0];
        #pragma unroll
        for (int ks = 0; ks < 2; ks++) {
            int k8 = ks * 8;
            const float* ar0 = &As[(rowbase + lr) * SA + k8 + lk];
            const float* ar1 = ar0 + 8 * SA;
            unsigned a0 = __float_as_uint(ar0[0]);
            unsigned a1 = __float_as_uint(ar1[0]);
            unsigned a2 = __float_as_uint(ar0[4]);
            unsigned a3 = __float_as_uint(ar1[4]);
            #pragma unroll
            for (int j = 0; j < 12; j++) {
                unsigned b0  = __float_as_uint(wb[(k8 + lk    ) * SW + j*8 + lr]);
                unsigned b1v = __float_as_uint(wb[(k8 + lk + 4) * SW + j*8 + lr]);
                mma_tf32(acc[j], a0, a1, a2, a3, b0, b1v);
            }
        }
        __syncthreads();   // mma reads done before next A stores / W reuse
    }

    // exact per-row ||q||: thread t and t^1 hold the two halves of row t>>1
    sq += __shfl_xor_sync(0xffffffffu, sq, 1);
    if ((tid & 1) == 0) qn[arow] = sqrtf(sq) * 1.02f;
    __syncthreads();

    // ---- epilogue: conservative window test per (row, col) ----
    float rc[3] = { g_p.rcf[0], g_p.rcf[1], g_p.rcf[2] };
    float wnml = g_p.wnml;
    int r0l = warp * 16 + lr, r1l = r0l + 8;
    float ml0 = qn[r0l] * wnml;
    float ml1 = qn[r1l] * wnml;
    unsigned msk0[3] = {0u,0u,0u}, msk1[3] = {0u,0u,0u};

    #pragma unroll
    for (int j = 0; j < 12; j++) {
        int cA = j*8 + 2*lk, cB = cA + 1;
        int dA = cA % 3, dB = cB % 3;
        float sdA = 0.5f * rc[dA], sdB = 0.5f * rc[dB];
        float bA = sboff[cA], bB = sboff[cB];

        float tA0 = (acc[j][0] + bA) * sdA;
        float tB0 = (acc[j][1] + bB) * sdB;
        float tA1 = (acc[j][2] + bA) * sdA;
        float tB1 = (acc[j][3] + bB) * sdB;
        float mA0 = ml0 * sdA + 1e-3f, mB0 = ml0 * sdB + 1e-3f;
        float mA1 = ml1 * sdA + 1e-3f, mB1 = ml1 * sdB + 1e-3f;

        if (tA0 > -1.f - mA0 && tA0 < 8.f + mA0) msk0[cA >> 5] |= 1u << (cA & 31);
        if (tB0 > -1.f - mB0 && tB0 < 8.f + mB0) msk0[cB >> 5] |= 1u << (cB & 31);
        if (tA1 > -1.f - mA1 && tA1 < 8.f + mA1) msk1[cA >> 5] |= 1u << (cA & 31);
        if (tB1 > -1.f - mB1 && tB1 < 8.f + mB1) msk1[cB >> 5] |= 1u << (cB & 31);
    }
    #pragma unroll
    for (int w = 0; w < 3; w++) {
        if (msk0[w]) atomicOr(&rowmask[r0l * 3 + w], msk0[w]);
        if (msk1[w]) atomicOr(&rowmask[r1l * 3 + w], msk1[w]);
    }
    __syncthreads();

    // candidate rows: exists p with bits 3p, 3p+1, 3p+2 all set
    if (tid < 128) {
        int row = m0 + tid;
        if (row < n) {
            unsigned w0 = rowmask[tid*3], w1 = rowmask[tid*3+1], w2 = rowmask[tid*3+2];
            if (w0 | w1 | w2) {
                bool any = false;
                #pragma unroll
                for (int p = 0; p < 32; p++) {
                    int c = 3 * p;
                    unsigned q0b = ((c < 32 ? w0 : (c < 64 ? w1 : w2)) >> (c & 31)) & 1u;
                    int c1i = c + 1;
                    unsigned q1b = ((c1i < 32 ? w0 : (c1i < 64 ? w1 : w2)) >> (c1i & 31)) & 1u;
                    int c2i = c + 2;
                    unsigned q2b = ((c2i < 32 ? w0 : (c2i < 64 ? w1 : w2)) >> (c2i & 31)) & 1u;
                    any |= (q0b & q1b & q2b) != 0u;
                }
                if (any) {
                    int slot = atomicAdd(&g_count, 1);
                    act_list[slot] = row;
                }
            }
        }
    }

    // fill out = b_out (exact for non-candidates; candidates overwritten later)
    for (int idx = tid; idx < 128 * 32; idx += 256) {
        int r  = idx >> 5;
        int c4 = (idx & 31) << 2;
        int orow = m0 + r;
        if (orow < n)
            *(float4*)(out + (size_t)orow * DM + c4) = *(const float4*)&sbout[c4];
    }
}

// ---------------- active rows: full exact fp32 recompute per row -------------
__global__ __launch_bounds__(128)
void k_active(const float* __restrict__ query, const int* __restrict__ coords,
              const float* __restrict__ value_fea,
              const float* __restrict__ W_off,  const float* __restrict__ b_off,
              const float* __restrict__ W_attn, const float* __restrict__ b_attn,
              const float* __restrict__ W_val,  const float* __restrict__ b_val,
              const float* __restrict__ W_out,  const float* __restrict__ b_out,
              const int* __restrict__ act_list, float* __restrict__ out, int n)
{
    __shared__ float sq[DM];
    __shared__ float slog[DM];
    __shared__ float sv[DM];
    __shared__ float spre[DM];
    __shared__ float sw[8];
    __shared__ int   sgi1;

    int tid = threadIdx.x;
    int cnt = g_count;

    for (int idx = blockIdx.x; idx < cnt; idx += gridDim.x) {
        int row = act_list[idx];
        sq[tid] = query[(size_t)row * DM + tid];
        __syncthreads();

        // exact logits [off | attn]
        {
            float a = 0.f;
            if (tid < 96) {
                #pragma unroll 8
                for (int k = 0; k < DM; k++)
                    a = fmaf(sq[k], W_off[k * 96 + tid], a);
                a += b_off[tid];
            } else {
                int c = tid - 96;
                #pragma unroll 8
                for (int k = 0; k < DM; k++)
                    a = fmaf(sq[k], W_attn[k * 32 + c], a);
                a += b_attn[c];
            }
            slog[tid] = a;
        }
        __syncthreads();

        // mask + softmax per head; gather index
        if (tid < 8) {
            int h = tid;
            float l[4], e[4];
            #pragma unroll
            for (int p = 0; p < 4; p++) l[p] = slog[96 + h*4 + p];
            float mx = fmaxf(fmaxf(l[0], l[1]), fmaxf(l[2], l[3]));
            float s = 0.f;
            #pragma unroll
            for (int p = 0; p < 4; p++) { e[p] = expf(l[p] - mx); s += e[p]; }
            float num = 0.f;
            #pragma unroll
            for (int p = 0; p < 4; p++) {
                int base = (h*4 + p) * 3;
                float t0 = (slog[base + 0] * g_p.rcf[0]) * 0.5f;
                float t1 = (slog[base + 1] * g_p.rcf[1]) * 0.5f;
                float t2 = (slog[base + 2] * g_p.rcf[2]) * 0.5f;
                int a0 = (int)t0, a1 = (int)t1, a2 = (int)t2;  // trunc toward 0
                unsigned u = (unsigned)a0 | (unsigned)a1 | (unsigned)a2;
                if (u < 8u) num += e[p];
            }
            sw[h] = num / s;
        }
        if (tid == 0) {
            int c0 = coords[3*row + 0], c1 = coords[3*row + 1], c2 = coords[3*row + 2];
            float i0 = (float)(c0 - g_p.minc[0]) * 0.125f;
            float i1 = (float)(c1 - g_p.minc[1]) * 0.125f;
            float i2 = (float)(c2 - g_p.minc[2]) * 0.125f;
            float flat = i0 * g_p.rv1f * g_p.rv0f + i1 * g_p.rv0f + i2;
            int gi = (int)floorf(flat);
            gi = gi < 0 ? 0 : (gi > n - 1 ? n - 1 : gi);
            sgi1 = gi;
        }
        __syncthreads();

        sv[tid] = value_fea[(size_t)sgi1 * DM + tid];
        __syncthreads();

        // value GEMV + head-weight scale
        {
            float a = 0.f;
            #pragma unroll 8
            for (int k = 0; k < DM; k++)
                a = fmaf(sv[k], W_val[k * DM + tid], a);
            spre[tid] = (a + b_val[tid]) * sw[tid >> 4];
        }
        __syncthreads();

        // out GEMV
        {
            float a = 0.f;
            #pragma unroll 8
            for (int k = 0; k < DM; k++)
                a = fmaf(spre[k], W_out[k * DM + tid], a);
            out[(size_t)row * DM + tid] = a + b_out[tid];
        }
        __syncthreads();
    }
}

// ---------------- launcher ---------------------------------------------------
extern "C" void kernel_launch(void* const* d_in, const int* in_sizes, int n_in,
                              void* d_out, int out_size)
{
    const float* query     = (const float*)d_in[0];
    const float* value_fea = (const float*)d_in[1];
    const int*   coords    = (const int*)  d_in[2];
    const float* W_off     = (const float*)d_in[3];
    const float* b_off     = (const float*)d_in[4];
    const float* W_attn    = (const float*)d_in[5];
    const float* b_attn    = (const float*)d_in[6];
    const float* W_val     = (const float*)d_in[7];
    const float* b_val     = (const float*)d_in[8];
    const float* W_out     = (const float*)d_in[9];
    const float* b_out     = (const float*)d_in[10];
    float* out = (float*)d_out;

    int n = in_sizes[0] / DM;
    if (n > NMAX) n = NMAX;

    int* gact = nullptr;
    cudaGetSymbolAddress((void**)&gact, g_active);

    int nb = (n + 127) / 128;

    // 5 launches
    k_setup <<<1, 256>>>(W_off);                 // init + W column-norm max
    k_minmax<<<592, 256>>>(coords, n);
    k_params<<<1, 1>>>(n);

    // TF32 tensor-core screen (certified truncation margin) + out=b_out fill
    k_screen<<<nb, 256>>>(query, W_off, b_off, b_out, gact, out, n);

    // exact end-to-end recompute of candidate rows
    k_active<<<512, 128>>>(query, coords, value_fea,
                           W_off, b_off, W_attn, b_attn,
                           W_val, b_val, W_out, b_out,
                           gact, out, n);
}